// round 13
// baseline (speedup 1.0000x reference)
#include <cuda_runtime.h>
#include <cuda_bf16.h>
#include <math.h>
#include <stdint.h>

#define BB 64
#define NN 40
#define WW 256
#define FIN 64
#define HH 4
#define CC 128
#define WKN 61
#define WPAD 64
#define W0 195
#define PP (BB*NN)
#define TCN_GRID 296

// ---------------- scratch (device globals; no cudaMalloc allowed) -------------
__device__ __align__(128) float g_cur[PP*WPAD*CC];
__device__ __align__(128) float g_last[PP*CC];      // final t=60 row per window
__device__ __align__(128) float g_ab [8*2*CC];
// bf16 hi/lo weights, uint4-packed fragments (hi.x,hi.y,lo.x,lo.y):
// index = (((conv*3+tap)*8+kt)*16+nt)*32+lane
__device__ __align__(128) uint4 g_wb4[8*3*8*16*32];

__device__ __forceinline__ float gelu_exact(float v){
    return 0.5f*v*(1.0f + erff(v*0.70710678118654752440f));
}

__device__ __forceinline__ void split_pair(float x, float y, uint32_t& hi, uint32_t& lo){
    __nv_bfloat162 h = __floats2bfloat162_rn(x, y);
    float hx = __bfloat162float(h.x), hy = __bfloat162float(h.y);
    __nv_bfloat162 l = __floats2bfloat162_rn(x - hx, y - hy);
    hi = *(uint32_t*)&h;
    lo = *(uint32_t*)&l;
}
__device__ __forceinline__ float2 join_pair(uint32_t hi, uint32_t lo){
    __nv_bfloat162 h = *reinterpret_cast<__nv_bfloat162*>(&hi);
    __nv_bfloat162 l = *reinterpret_cast<__nv_bfloat162*>(&lo);
    return make_float2(__bfloat162float(h.x) + __bfloat162float(l.x),
                       __bfloat162float(h.y) + __bfloat162float(l.y));
}

__device__ __forceinline__ uint32_t smem_u32(const void* p){
    uint32_t a;
    asm("{ .reg .u64 t; cvta.to.shared.u64 t, %1; cvt.u32.u64 %0, t; }" : "=r"(a) : "l"(p));
    return a;
}

#define MMA_BF16(c, a, bx, by) \
    asm volatile("mma.sync.aligned.m16n8k16.row.col.f32.bf16.bf16.f32 " \
        "{%0,%1,%2,%3}, {%4,%5,%6,%7}, {%8,%9}, {%0,%1,%2,%3};" \
        : "+f"((c)[0]), "+f"((c)[1]), "+f"((c)[2]), "+f"((c)[3]) \
        : "r"((a)[0]), "r"((a)[1]), "r"((a)[2]), "r"((a)[3]), \
          "r"(bx), "r"(by))

#define CP_ASYNC16(saddr, gptr) \
    asm volatile("cp.async.cg.shared.global [%0], [%1], 16;" :: "r"(saddr), "l"(gptr) : "memory")
#define CP_COMMIT() asm volatile("cp.async.commit_group;" ::: "memory")
#define CP_WAIT1()  asm volatile("cp.async.wait_group 1;" ::: "memory")
#define CP_WAIT0()  asm volatile("cp.async.wait_group 0;" ::: "memory")

// ---------------- prep: fused BN params ---------------------------------------
__global__ void prep_ab_kernel(const float* c1b, const float* c2b,
    const float* bn1s, const float* bn1b, const float* bn1m, const float* bn1v,
    const float* bn2s, const float* bn2b, const float* bn2m, const float* bn2v){
    int i = blockIdx.x*blockDim.x + threadIdx.x;
    if (i >= 8*CC) return;
    int c = i >> 7, co = i & 127;
    int l = c >> 1;
    const float *s, *bb, *m, *v, *bias;
    if (c & 1){ s=bn2s; bb=bn2b; m=bn2m; v=bn2v; bias=c2b; }
    else      { s=bn1s; bb=bn1b; m=bn1m; v=bn1v; bias=c1b; }
    int gi = l*CC + co;
    float alpha = s[gi]*rsqrtf(v[gi] + 1e-5f);
    float beta  = (bias[gi] - m[gi])*alpha + bb[gi];
    g_ab[c*2*CC + co]      = alpha;
    g_ab[c*2*CC + CC + co] = beta;
}

// ------- prep: bf16 hi/lo weights, uint4 fragments in B-fragment order --------
__global__ void prep_wb_kernel(const float* c1w, const float* c2w){
    int i = blockIdx.x*blockDim.x + threadIdx.x;
    if (i >= 8*3*8*16*32) return;
    int lane = i & 31;
    int nt   = (i >> 5) & 15;
    int kt   = (i >> 9) & 7;
    int tc   = i >> 12;
    int tap  = tc % 3;
    int c    = tc / 3;
    int l = c >> 1;
    const float* src = (c & 1) ? c2w : c1w;          // (L, CO, CI, K)
    int co  = nt*8 + (lane >> 2);
    int ci0 = kt*16 + (lane & 3)*2;
    float w00 = src[((l*CC+co)*CC + ci0    )*3 + tap];
    float w01 = src[((l*CC+co)*CC + ci0 + 1)*3 + tap];
    float w10 = src[((l*CC+co)*CC + ci0 + 8)*3 + tap];
    float w11 = src[((l*CC+co)*CC + ci0 + 9)*3 + tap];
    uint32_t h0, l0, h1, l1;
    split_pair(w00, w01, h0, l0);
    split_pair(w10, w11, h1, l1);
    g_wb4[i] = make_uint4(h0, h1, l0, l1);
}

// ------- fused GAT: projection + e_src/e_dst + attention + LayerNorm ----------
// smem floats: sh_h 5120 | sh_attn 6400 (x-staging / attnT / LN scratch) |
//              es 160 (later LN stats) | ed 160 | ln 256 (+ adj bytes)
#define ATTN_SMEM_BYTES (12096*4 + 1600)
__global__ void __launch_bounds__(256) gatt_kernel(
        const float* __restrict__ x, const float* __restrict__ gat_w,
        const float* __restrict__ a_src, const float* __restrict__ a_dst,
        const float* __restrict__ adj,
        const float* __restrict__ ln_g, const float* __restrict__ ln_b){
    extern __shared__ float sm[];
    float* sh_h    = sm;            // [j][c]
    float* sh_attn = sm + 5120;     // x staging; then attnT [j][h][n]; then LN scratch
    float* sh_es   = sm + 11520;
    float* sh_ed   = sm + 11680;
    float* sh_ln   = sm + 11840;
    unsigned char* sh_adj = (unsigned char*)(sm + 12096);
    int tid = threadIdx.x;
    int wk = blockIdx.x, b = blockIdx.y;
    int c = tid & 127, half = tid >> 7;
    int head = (tid >> 5) & 3;
    int lane = tid & 31;

    // ---- stage x (40 x 64) into scratch; load constants ----
    float* sh_x = sh_attn;          // 2560 floats, freed before softmax writes
    for (int i = tid; i < NN*FIN; i += 256){
        int j = i >> 6, f = i & 63;
        sh_x[i] = x[(((size_t)(b*NN + j))*WW + (W0 + wk))*FIN + f];
    }
    for (int i = tid; i < NN*NN; i += 256) sh_adj[i] = (adj[i] != 0.f);
    for (int i = tid; i < CC; i += 256){ sh_ln[i] = ln_g[i]; sh_ln[CC + i] = ln_b[i]; }

    // gat_w row for this thread's channel, in registers
    float wreg[FIN];
    #pragma unroll
    for (int f4 = 0; f4 < FIN/4; f4++){
        float4 w = *(const float4*)&gat_w[c*FIN + f4*4];
        wreg[f4*4+0] = w.x; wreg[f4*4+1] = w.y;
        wreg[f4*4+2] = w.z; wreg[f4*4+3] = w.w;
    }
    float asv = a_src[c], adv = a_dst[c];
    __syncthreads();

    // ---- projection: thread computes h[j][c] for its 20 nodes + es/ed ----
    #pragma unroll 1
    for (int j20 = 0; j20 < 20; j20++){
        int j = half*20 + j20;
        const float* xr = &sh_x[j*FIN];
        float a0 = 0.f, a1 = 0.f, a2 = 0.f, a3 = 0.f;
        #pragma unroll
        for (int f = 0; f < FIN; f += 4){
            float4 xv = *(const float4*)&xr[f];
            a0 = fmaf(xv.x, wreg[f+0], a0);
            a1 = fmaf(xv.y, wreg[f+1], a1);
            a2 = fmaf(xv.z, wreg[f+2], a2);
            a3 = fmaf(xv.w, wreg[f+3], a3);
        }
        float hv = (a0 + a1) + (a2 + a3);
        sh_h[j*CC + c] = hv;
        float es = hv*asv, ed = hv*adv;
        #pragma unroll
        for (int o = 16; o; o >>= 1){
            es += __shfl_xor_sync(0xffffffffu, es, o);
            ed += __shfl_xor_sync(0xffffffffu, ed, o);
        }
        if (lane == 0){
            sh_es[j*HH + head] = es;
            sh_ed[j*HH + head] = ed;
        }
    }
    __syncthreads();

    // ---- softmax per (n, h); store transposed [j][h][n] ----
    if (tid < NN*HH){
        int n = tid >> 2, h = tid & 3;
        float esrc = sh_es[tid];
        float mx = -1e30f;
        #pragma unroll
        for (int j = 0; j < NN; j++){
            float s = esrc + sh_ed[j*HH + h];
            s = s > 0.f ? s : 0.2f*s;
            if (!sh_adj[n*NN + j]) s = -1e9f;
            mx = fmaxf(mx, s);
        }
        float sum = 0.f;
        #pragma unroll
        for (int j = 0; j < NN; j++){
            float s = esrc + sh_ed[j*HH + h];
            s = s > 0.f ? s : 0.2f*s;
            if (!sh_adj[n*NN + j]) s = -1e9f;
            float e = expf(s - mx);
            sum += e;
            sh_attn[(j*HH + h)*NN + n] = e;
        }
        float inv = 1.f/sum;
        #pragma unroll
        for (int j = 0; j < NN; j++) sh_attn[(j*HH + h)*NN + n] *= inv;
    }
    __syncthreads();

    // ---- aggregate: thread handles n = half*20 + q ----
    float acc[20];
    #pragma unroll
    for (int q = 0; q < 20; q++) acc[q] = 0.f;
    #pragma unroll 1
    for (int jc = 0; jc < 2; jc++){
        float hreg[20];
        #pragma unroll
        for (int j = 0; j < 20; j++) hreg[j] = sh_h[(jc*20 + j)*CC + c];
        #pragma unroll
        for (int j = 0; j < 20; j++){
            int jj = jc*20 + j;
            float hv = hreg[j];
            const float2* ap = (const float2*)&sh_attn[(jj*HH + head)*NN + half*20];
            #pragma unroll
            for (int t = 0; t < 10; t++){
                float2 av = ap[t];
                acc[2*t]   = fmaf(av.x, hv, acc[2*t]);
                acc[2*t+1] = fmaf(av.y, hv, acc[2*t+1]);
            }
        }
    }
    __syncthreads();

    // ---- LN stats via scratch + warp reductions ----
    float* sh_sc = sh_attn;
    #pragma unroll
    for (int q = 0; q < 20; q++)
        sh_sc[(half*20 + q)*CC + c] = acc[q];
    __syncthreads();
    {
        int wd = tid >> 5, ln = tid & 31;
        #pragma unroll
        for (int k = 0; k < 5; k++){
            int n = wd*5 + k;
            float4 v = *(const float4*)&sh_sc[n*CC + ln*4];
            float s1 = (v.x + v.y) + (v.z + v.w);
            float s2 = (v.x*v.x + v.y*v.y) + (v.z*v.z + v.w*v.w);
            #pragma unroll
            for (int o = 16; o; o >>= 1){
                s1 += __shfl_xor_sync(0xffffffffu, s1, o);
                s2 += __shfl_xor_sync(0xffffffffu, s2, o);
            }
            if (ln == 0){
                float mu  = s1*(1.f/CC);
                float var = s2*(1.f/CC) - mu*mu;
                sh_es[n*2]     = mu;
                sh_es[n*2 + 1] = rsqrtf(var + 1e-5f);
            }
        }
    }
    __syncthreads();

    float lg = sh_ln[c], lb = sh_ln[CC + c];
    #pragma unroll
    for (int q = 0; q < 20; q++){
        int n = half*20 + q;
        float mu = sh_es[n*2], inv = sh_es[n*2 + 1];
        g_cur[((b*NN + n)*WPAD + wk)*CC + c] = (acc[q] - mu)*inv*lg + lb;
    }
}

// ======= persistent fused TCN: CTA loops over windows, pipeline continuous ====
#define HALO 16
#define PIT16 68
#define TCN_SMEM (80*PIT16*2*4 + 4096*16)

__global__ void __launch_bounds__(256) tcn_fused_kernel(){
    extern __shared__ uint32_t smw[];
    uint32_t* s_hi = smw;                        // 80*68
    uint32_t* s_lo = smw + 80*PIT16;             // 80*68
    uint4*    s_b  = (uint4*)(smw + 2*80*PIT16); // 2 x 2048 uint4
    const uint32_t sb_u32 = smem_u32(s_b);
    int tid = threadIdx.x, lane = tid & 31, wid = tid >> 5;
    int wm = wid & 3, wn = wid >> 2;             // identity mapping (measured best)
    int r = lane >> 2, q = lane & 3;
    int r0 = wm*16 + r, r1 = r0 + 8;
    int cb = wn*64 + q*2;

    const int nwin = (PP - blockIdx.x + (TCN_GRID-1))/TCN_GRID;
    const int total_halves = nwin*48;

    // issue one 32KB half stage: weight src index s (0..47), buffer parity bp
    auto issue_half = [&](int s, int bp){
        const uint4* src = g_wb4 + (size_t)s*2048 + tid;
        uint32_t dst = sb_u32 + (uint32_t)(bp*2048 + tid)*16u;
        #pragma unroll
        for (int i = 0; i < 8; i++)
            CP_ASYNC16(dst + (uint32_t)(i*256*16), (const void*)(src + i*256));
        CP_COMMIT();
    };

    issue_half(0, 0);          // prologue: half 0 in flight
    int a = 0;                 // absolute half counter (next to compute)

    // zero halo once (rows 0..15 are never overwritten)
    for (int i = tid; i < HALO*PIT16; i += 256){ s_hi[i] = 0u; s_lo[i] = 0u; }

    const int DIL_[8] = {1,1,2,2,4,4,8,8};
    const int TLO_[8] = {2,4,8,12,20,28,44,60};
    float res[8][4];

    #pragma unroll 1
    for (int wdx = 0; wdx < nwin; wdx++){
        int p = blockIdx.x + wdx*TCN_GRID;
        __syncthreads();   // prior window's g_last read / epilogue done before restage
        // stage window (rows 61..63 zero: not produced by attn)
        for (int i = tid; i < 64*64; i += 256){
            int t = i >> 6, cp = i & 63;
            float2 v = (t <= 60) ? *(const float2*)&g_cur[((size_t)p*WPAD + t)*CC + cp*2]
                                 : make_float2(0.f, 0.f);
            uint32_t h, l;
            split_pair(v.x, v.y, h, l);
            s_hi[(HALO + t)*PIT16 + cp] = h;
            s_lo[(HALO + t)*PIT16 + cp] = l;
        }
        __syncthreads();

        #pragma unroll 1
        for (int cv = 0; cv < 8; cv++){
            const int D = DIL_[cv], tlo = TLO_[cv];
            const bool second = (cv & 1);
            bool active = (wm*16 + 15) >= tlo;

            if (!second){
                #pragma unroll
                for (int nt = 0; nt < 8; nt++){
                    int cw = (cb + nt*8) >> 1;
                    int w0 = (HALO + r0)*PIT16 + cw;
                    int w1 = (HALO + r1)*PIT16 + cw;
                    float2 q0 = join_pair(s_hi[w0], s_lo[w0]);
                    float2 q1 = join_pair(s_hi[w1], s_lo[w1]);
                    res[nt][0] = q0.x; res[nt][1] = q0.y;
                    res[nt][2] = q1.x; res[nt][3] = q1.y;
                }
            }

            float acc[8][4];
            #pragma unroll
            for (int nt = 0; nt < 8; nt++)
                #pragma unroll
                for (int e = 0; e < 4; e++) acc[nt][e] = 0.f;

            #pragma unroll 1
            for (int tap = 0; tap < 3; tap++){
                int rowb = (HALO + wm*16 + r + (tap - 2)*D)*PIT16 + q;
                #pragma unroll 1
                for (int hf = 0; hf < 2; hf++){
                    __syncthreads();               // readers of other buffer done
                    if (a + 1 < total_halves){
                        int nx = a + 1;
                        issue_half((nx % 48), (nx & 1));
                        CP_WAIT1();
                    } else {
                        CP_WAIT0();
                    }
                    __syncthreads();               // staged data visible

                    if (active){
                        const uint4* bbase = s_b + (size_t)(a & 1)*2048;
                        #pragma unroll
                        for (int kk = 0; kk < 4; kk++){
                            int kt = hf*4 + kk;
                            int w = rowb + kt*8;
                            uint32_t ah[4], al[4];
                            ah[0] = s_hi[w];              ah[1] = s_hi[w + 8*PIT16];
                            ah[2] = s_hi[w + 4];          ah[3] = s_hi[w + 8*PIT16 + 4];
                            al[0] = s_lo[w];              al[1] = s_lo[w + 8*PIT16];
                            al[2] = s_lo[w + 4];          al[3] = s_lo[w + 8*PIT16 + 4];
                            const uint4* bp = bbase + (size_t)(kk*16 + wn*8)*32 + lane;
                            #pragma unroll
                            for (int nt = 0; nt < 8; nt++){
                                uint4 bb = bp[nt*32];
                                MMA_BF16(acc[nt], ah, bb.x, bb.y);
                                MMA_BF16(acc[nt], al, bb.x, bb.y);
                                MMA_BF16(acc[nt], ah, bb.z, bb.w);
                            }
                        }
                    }
                    a++;
                }
            }
            __syncthreads();   // all A reads done before input buffers are overwritten

            if (active){
                const float* ab = &g_ab[cv*2*CC];
                #pragma unroll
                for (int nt = 0; nt < 8; nt++){
                    int c = cb + nt*8;
                    int w0 = (HALO + r0)*PIT16 + (c >> 1);
                    int w1 = (HALO + r1)*PIT16 + (c >> 1);
                    float a0 = ab[c], a1 = ab[c+1], b0 = ab[CC+c], b1 = ab[CC+c+1];
                    float y00 = gelu_exact(fmaf(acc[nt][0], a0, b0));
                    float y01 = gelu_exact(fmaf(acc[nt][1], a1, b1));
                    float y10 = gelu_exact(fmaf(acc[nt][2], a0, b0));
                    float y11 = gelu_exact(fmaf(acc[nt][3], a1, b1));
                    if (second){
                        y00 = gelu_exact(y00 + res[nt][0]);
                        y01 = gelu_exact(y01 + res[nt][1]);
                        y10 = gelu_exact(y10 + res[nt][2]);
                        y11 = gelu_exact(y11 + res[nt][3]);
                    }
                    uint32_t h0, l0, h1, l1;
                    split_pair(y00, y01, h0, l0);
                    split_pair(y10, y11, h1, l1);
                    s_hi[w0] = h0; s_lo[w0] = l0;
                    s_hi[w1] = h1; s_lo[w1] = l1;
                }
            }
        }
        __syncthreads();

        // only t=60 row is needed downstream (value = hi + lo)
        if (tid < CC){
            int w = (HALO + 60)*PIT16 + (tid >> 1);
            float2 v = join_pair(s_hi[w], s_lo[w]);
            g_last[(size_t)p*CC + tid] = (tid & 1) ? v.y : v.x;
        }
    }
}

// ---------------- head: FC(128->128)+GELU, FC(128->1) -------------------------
__global__ void head_kernel(const float* __restrict__ f1w, const float* __restrict__ f1b,
                            const float* __restrict__ f2w, const float* __restrict__ f2b,
                            float* __restrict__ out){
    __shared__ float tv[CC];
    __shared__ float red[4];
    int tid = threadIdx.x;
    int b = blockIdx.x / 7, n = blockIdx.x % 7;
    tv[tid] = g_last[((size_t)(b*NN + n))*CC + tid];
    __syncthreads();
    float z = f1b[tid];
    #pragma unroll 4
    for (int c = 0; c < CC; c++) z = fmaf(f1w[tid*CC + c], tv[c], z);
    z = gelu_exact(z);
    float r = z*f2w[tid];
    #pragma unroll
    for (int o = 16; o; o >>= 1) r += __shfl_xor_sync(0xffffffffu, r, o);
    if ((tid & 31) == 0) red[tid >> 5] = r;
    __syncthreads();
    if (tid == 0) out[blockIdx.x] = red[0] + red[1] + red[2] + red[3] + f2b[0];
}

// -------------------------------------------------------------------------------
extern "C" void kernel_launch(void* const* d_in, const int* in_sizes, int n_in,
                              void* d_out, int out_size){
    const float* x     = (const float*)d_in[0];
    const float* adj   = (const float*)d_in[1];
    const float* gat_w = (const float*)d_in[2];
    const float* a_src = (const float*)d_in[3];
    const float* a_dst = (const float*)d_in[4];
    const float* ln_g  = (const float*)d_in[5];
    const float* ln_b  = (const float*)d_in[6];
    const float* c1w   = (const float*)d_in[7];
    const float* c1b   = (const float*)d_in[8];
    const float* c2w   = (const float*)d_in[9];
    const float* c2b   = (const float*)d_in[10];
    const float* bn1s  = (const float*)d_in[11];
    const float* bn1b  = (const float*)d_in[12];
    const float* bn1m  = (const float*)d_in[13];
    const float* bn1v  = (const float*)d_in[14];
    const float* bn2s  = (const float*)d_in[15];
    const float* bn2b  = (const float*)d_in[16];
    const float* bn2m  = (const float*)d_in[17];
    const float* bn2v  = (const float*)d_in[18];
    const float* f1w   = (const float*)d_in[19];
    const float* f1b   = (const float*)d_in[20];
    const float* f2w   = (const float*)d_in[21];
    const float* f2b   = (const float*)d_in[22];
    float* out = (float*)d_out;

    cudaFuncSetAttribute(gatt_kernel,      cudaFuncAttributeMaxDynamicSharedMemorySize, ATTN_SMEM_BYTES);
    cudaFuncSetAttribute(tcn_fused_kernel, cudaFuncAttributeMaxDynamicSharedMemorySize, TCN_SMEM);

    prep_ab_kernel<<<4, 256>>>(c1b, c2b, bn1s, bn1b, bn1m, bn1v, bn2s, bn2b, bn2m, bn2v);
    prep_wb_kernel<<<(8*3*8*16*32)/256, 256>>>(c1w, c2w);
    gatt_kernel<<<dim3(WKN, BB), 256, ATTN_SMEM_BYTES>>>(x, gat_w, a_src, a_dst,
                                                         adj, ln_g, ln_b);
    tcn_fused_kernel<<<TCN_GRID, 256, TCN_SMEM>>>();
    head_kernel<<<BB*7, 128>>>(f1w, f1b, f2w, f2b, out);
}

// round 14
// speedup vs baseline: 1.0681x; 1.0681x over previous
#include <cuda_runtime.h>
#include <cuda_bf16.h>
#include <math.h>
#include <stdint.h>

#define BB 64
#define NN 40
#define WW 256
#define FIN 64
#define HH 4
#define CC 128
#define WKN 61
#define WPAD 64
#define W0 195
#define PP (BB*NN)

// ---------------- scratch (device globals; no cudaMalloc allowed) -------------
__device__ __align__(128) float g_cur[PP*WPAD*CC];
__device__ __align__(128) float g_last[PP*CC];      // final t=60 row per window
__device__ __align__(128) float g_ab [8*2*CC];
// bf16 hi/lo weights, uint4-packed fragments (hi.x,hi.y,lo.x,lo.y):
// index = (((conv*3+tap)*8+kt)*16+nt)*32+lane
__device__ __align__(128) uint4 g_wb4[8*3*8*16*32];

__device__ __forceinline__ float gelu_exact(float v){
    return 0.5f*v*(1.0f + erff(v*0.70710678118654752440f));
}

__device__ __forceinline__ void split_pair(float x, float y, uint32_t& hi, uint32_t& lo){
    __nv_bfloat162 h = __floats2bfloat162_rn(x, y);
    float hx = __bfloat162float(h.x), hy = __bfloat162float(h.y);
    __nv_bfloat162 l = __floats2bfloat162_rn(x - hx, y - hy);
    hi = *(uint32_t*)&h;
    lo = *(uint32_t*)&l;
}
__device__ __forceinline__ float2 join_pair(uint32_t hi, uint32_t lo){
    __nv_bfloat162 h = *reinterpret_cast<__nv_bfloat162*>(&hi);
    __nv_bfloat162 l = *reinterpret_cast<__nv_bfloat162*>(&lo);
    return make_float2(__bfloat162float(h.x) + __bfloat162float(l.x),
                       __bfloat162float(h.y) + __bfloat162float(l.y));
}

__device__ __forceinline__ uint32_t smem_u32(const void* p){
    uint32_t a;
    asm("{ .reg .u64 t; cvta.to.shared.u64 t, %1; cvt.u32.u64 %0, t; }" : "=r"(a) : "l"(p));
    return a;
}

#define MMA_BF16(c, a, bx, by) \
    asm volatile("mma.sync.aligned.m16n8k16.row.col.f32.bf16.bf16.f32 " \
        "{%0,%1,%2,%3}, {%4,%5,%6,%7}, {%8,%9}, {%0,%1,%2,%3};" \
        : "+f"((c)[0]), "+f"((c)[1]), "+f"((c)[2]), "+f"((c)[3]) \
        : "r"((a)[0]), "r"((a)[1]), "r"((a)[2]), "r"((a)[3]), \
          "r"(bx), "r"(by))

#define CP_ASYNC16(saddr, gptr) \
    asm volatile("cp.async.cg.shared.global [%0], [%1], 16;" :: "r"(saddr), "l"(gptr) : "memory")
#define CP_COMMIT() asm volatile("cp.async.commit_group;" ::: "memory")
#define CP_WAIT1()  asm volatile("cp.async.wait_group 1;" ::: "memory")
#define CP_WAIT0()  asm volatile("cp.async.wait_group 0;" ::: "memory")

// ---------------- prep: fused BN params ---------------------------------------
__global__ void prep_ab_kernel(const float* c1b, const float* c2b,
    const float* bn1s, const float* bn1b, const float* bn1m, const float* bn1v,
    const float* bn2s, const float* bn2b, const float* bn2m, const float* bn2v){
    int i = blockIdx.x*blockDim.x + threadIdx.x;
    if (i >= 8*CC) return;
    int c = i >> 7, co = i & 127;
    int l = c >> 1;
    const float *s, *bb, *m, *v, *bias;
    if (c & 1){ s=bn2s; bb=bn2b; m=bn2m; v=bn2v; bias=c2b; }
    else      { s=bn1s; bb=bn1b; m=bn1m; v=bn1v; bias=c1b; }
    int gi = l*CC + co;
    float alpha = s[gi]*rsqrtf(v[gi] + 1e-5f);
    float beta  = (bias[gi] - m[gi])*alpha + bb[gi];
    g_ab[c*2*CC + co]      = alpha;
    g_ab[c*2*CC + CC + co] = beta;
}

// ------- prep: bf16 hi/lo weights, uint4 fragments in B-fragment order --------
__global__ void prep_wb_kernel(const float* c1w, const float* c2w){
    int i = blockIdx.x*blockDim.x + threadIdx.x;
    if (i >= 8*3*8*16*32) return;
    int lane = i & 31;
    int nt   = (i >> 5) & 15;
    int kt   = (i >> 9) & 7;
    int tc   = i >> 12;
    int tap  = tc % 3;
    int c    = tc / 3;
    int l = c >> 1;
    const float* src = (c & 1) ? c2w : c1w;          // (L, CO, CI, K)
    int co  = nt*8 + (lane >> 2);
    int ci0 = kt*16 + (lane & 3)*2;
    float w00 = src[((l*CC+co)*CC + ci0    )*3 + tap];
    float w01 = src[((l*CC+co)*CC + ci0 + 1)*3 + tap];
    float w10 = src[((l*CC+co)*CC + ci0 + 8)*3 + tap];
    float w11 = src[((l*CC+co)*CC + ci0 + 9)*3 + tap];
    uint32_t h0, l0, h1, l1;
    split_pair(w00, w01, h0, l0);
    split_pair(w10, w11, h1, l1);
    g_wb4[i] = make_uint4(h0, h1, l0, l1);
}

// ------- fused GAT: projection + e_src/e_dst + attention + LayerNorm ----------
#define ATTN_SMEM_BYTES (12096*4 + 1600)
__global__ void __launch_bounds__(256) gatt_kernel(
        const float* __restrict__ x, const float* __restrict__ gat_w,
        const float* __restrict__ a_src, const float* __restrict__ a_dst,
        const float* __restrict__ adj,
        const float* __restrict__ ln_g, const float* __restrict__ ln_b){
    extern __shared__ float sm[];
    float* sh_h    = sm;            // [j][c]
    float* sh_attn = sm + 5120;     // x staging; then attnT [j][h][n]; then LN scratch
    float* sh_es   = sm + 11520;
    float* sh_ed   = sm + 11680;
    float* sh_ln   = sm + 11840;
    unsigned char* sh_adj = (unsigned char*)(sm + 12096);
    int tid = threadIdx.x;
    int wk = blockIdx.x, b = blockIdx.y;
    int c = tid & 127, half = tid >> 7;
    int head = (tid >> 5) & 3;
    int lane = tid & 31;

    // ---- stage x (40 x 64) into scratch; load constants ----
    float* sh_x = sh_attn;          // 2560 floats, freed before softmax writes
    for (int i = tid; i < NN*FIN; i += 256){
        int j = i >> 6, f = i & 63;
        sh_x[i] = x[(((size_t)(b*NN + j))*WW + (W0 + wk))*FIN + f];
    }
    for (int i = tid; i < NN*NN; i += 256) sh_adj[i] = (adj[i] != 0.f);
    for (int i = tid; i < CC; i += 256){ sh_ln[i] = ln_g[i]; sh_ln[CC + i] = ln_b[i]; }

    float wreg[FIN];
    #pragma unroll
    for (int f4 = 0; f4 < FIN/4; f4++){
        float4 w = *(const float4*)&gat_w[c*FIN + f4*4];
        wreg[f4*4+0] = w.x; wreg[f4*4+1] = w.y;
        wreg[f4*4+2] = w.z; wreg[f4*4+3] = w.w;
    }
    float asv = a_src[c], adv = a_dst[c];
    __syncthreads();

    // ---- projection: thread computes h[j][c] for its 20 nodes + es/ed ----
    #pragma unroll 1
    for (int j20 = 0; j20 < 20; j20++){
        int j = half*20 + j20;
        const float* xr = &sh_x[j*FIN];
        float a0 = 0.f, a1 = 0.f, a2 = 0.f, a3 = 0.f;
        #pragma unroll
        for (int f = 0; f < FIN; f += 4){
            float4 xv = *(const float4*)&xr[f];
            a0 = fmaf(xv.x, wreg[f+0], a0);
            a1 = fmaf(xv.y, wreg[f+1], a1);
            a2 = fmaf(xv.z, wreg[f+2], a2);
            a3 = fmaf(xv.w, wreg[f+3], a3);
        }
        float hv = (a0 + a1) + (a2 + a3);
        sh_h[j*CC + c] = hv;
        float es = hv*asv, ed = hv*adv;
        #pragma unroll
        for (int o = 16; o; o >>= 1){
            es += __shfl_xor_sync(0xffffffffu, es, o);
            ed += __shfl_xor_sync(0xffffffffu, ed, o);
        }
        if (lane == 0){
            sh_es[j*HH + head] = es;
            sh_ed[j*HH + head] = ed;
        }
    }
    __syncthreads();

    // ---- softmax per (n, h); store transposed [j][h][n] ----
    if (tid < NN*HH){
        int n = tid >> 2, h = tid & 3;
        float esrc = sh_es[tid];
        float mx = -1e30f;
        #pragma unroll
        for (int j = 0; j < NN; j++){
            float s = esrc + sh_ed[j*HH + h];
            s = s > 0.f ? s : 0.2f*s;
            if (!sh_adj[n*NN + j]) s = -1e9f;
            mx = fmaxf(mx, s);
        }
        float sum = 0.f;
        #pragma unroll
        for (int j = 0; j < NN; j++){
            float s = esrc + sh_ed[j*HH + h];
            s = s > 0.f ? s : 0.2f*s;
            if (!sh_adj[n*NN + j]) s = -1e9f;
            float e = expf(s - mx);
            sum += e;
            sh_attn[(j*HH + h)*NN + n] = e;
        }
        float inv = 1.f/sum;
        #pragma unroll
        for (int j = 0; j < NN; j++) sh_attn[(j*HH + h)*NN + n] *= inv;
    }
    __syncthreads();

    // ---- aggregate: thread handles n = half*20 + q ----
    float acc[20];
    #pragma unroll
    for (int q = 0; q < 20; q++) acc[q] = 0.f;
    #pragma unroll 1
    for (int jc = 0; jc < 2; jc++){
        float hreg[20];
        #pragma unroll
        for (int j = 0; j < 20; j++) hreg[j] = sh_h[(jc*20 + j)*CC + c];
        #pragma unroll
        for (int j = 0; j < 20; j++){
            int jj = jc*20 + j;
            float hv = hreg[j];
            const float2* ap = (const float2*)&sh_attn[(jj*HH + head)*NN + half*20];
            #pragma unroll
            for (int t = 0; t < 10; t++){
                float2 av = ap[t];
                acc[2*t]   = fmaf(av.x, hv, acc[2*t]);
                acc[2*t+1] = fmaf(av.y, hv, acc[2*t+1]);
            }
        }
    }
    __syncthreads();

    // ---- LN stats via scratch + warp reductions ----
    float* sh_sc = sh_attn;
    #pragma unroll
    for (int q = 0; q < 20; q++)
        sh_sc[(half*20 + q)*CC + c] = acc[q];
    __syncthreads();
    {
        int wd = tid >> 5, ln = tid & 31;
        #pragma unroll
        for (int k = 0; k < 5; k++){
            int n = wd*5 + k;
            float4 v = *(const float4*)&sh_sc[n*CC + ln*4];
            float s1 = (v.x + v.y) + (v.z + v.w);
            float s2 = (v.x*v.x + v.y*v.y) + (v.z*v.z + v.w*v.w);
            #pragma unroll
            for (int o = 16; o; o >>= 1){
                s1 += __shfl_xor_sync(0xffffffffu, s1, o);
                s2 += __shfl_xor_sync(0xffffffffu, s2, o);
            }
            if (ln == 0){
                float mu  = s1*(1.f/CC);
                float var = s2*(1.f/CC) - mu*mu;
                sh_es[n*2]     = mu;
                sh_es[n*2 + 1] = rsqrtf(var + 1e-5f);
            }
        }
    }
    __syncthreads();

    float lg = sh_ln[c], lb = sh_ln[CC + c];
    #pragma unroll
    for (int q = 0; q < 20; q++){
        int n = half*20 + q;
        float mu = sh_es[n*2], inv = sh_es[n*2 + 1];
        g_cur[((b*NN + n)*WPAD + wk)*CC + c] = (acc[q] - mu)*inv*lg + lb;
    }
}

// ======= fused TCN: all 8 convs in one CTA per window, smem-resident ==========
#define HALO 16
#define PIT16 68
#define TCN_SMEM (80*PIT16*2*4 + 4096*16)

__global__ void __launch_bounds__(256) tcn_fused_kernel(){
    extern __shared__ uint32_t smw[];
    uint32_t* s_hi = smw;                        // 80*68
    uint32_t* s_lo = smw + 80*PIT16;             // 80*68
    uint4*    s_b  = (uint4*)(smw + 2*80*PIT16); // 2 x 2048 uint4
    const uint32_t sb_u32 = smem_u32(s_b);
    int tid = threadIdx.x, lane = tid & 31, wid = tid >> 5;
    int p = blockIdx.x;
    int wm = wid & 3, wn = wid >> 2;             // identity mapping (measured best)
    int r = lane >> 2, q = lane & 3;
    int r0 = wm*16 + r, r1 = r0 + 8;
    int cb = wn*64 + q*2;

    auto issue_half = [&](int hc){
        const uint4* src = g_wb4 + (size_t)hc*2048 + tid;
        uint32_t dst = sb_u32 + (uint32_t)((hc & 1)*2048 + tid)*16u;
        #pragma unroll
        for (int i = 0; i < 8; i++)
            CP_ASYNC16(dst + (uint32_t)(i*256*16), (const void*)(src + i*256));
        CP_COMMIT();
    };

    issue_half(0);
    int hc = 1;

    for (int i = tid; i < HALO*PIT16; i += 256){ s_hi[i] = 0u; s_lo[i] = 0u; }
    for (int i = tid; i < 64*64; i += 256){
        int t = i >> 6, cp = i & 63;
        float2 v = (t <= 60) ? *(const float2*)&g_cur[((size_t)p*WPAD + t)*CC + cp*2]
                             : make_float2(0.f, 0.f);
        uint32_t h, l;
        split_pair(v.x, v.y, h, l);
        s_hi[(HALO + t)*PIT16 + cp] = h;
        s_lo[(HALO + t)*PIT16 + cp] = l;
    }
    __syncthreads();

    const int DIL_[8] = {1,1,2,2,4,4,8,8};
    const int TLO_[8] = {2,4,8,12,20,28,44,60};

    float res[8][4];

    #pragma unroll 1
    for (int cv = 0; cv < 8; cv++){
        const int D = DIL_[cv], tlo = TLO_[cv];
        const bool second = (cv & 1);
        bool active = (wm*16 + 15) >= tlo;

        if (!second){
            #pragma unroll
            for (int nt = 0; nt < 8; nt++){
                int cw = (cb + nt*8) >> 1;
                int w0 = (HALO + r0)*PIT16 + cw;
                int w1 = (HALO + r1)*PIT16 + cw;
                float2 q0 = join_pair(s_hi[w0], s_lo[w0]);
                float2 q1 = join_pair(s_hi[w1], s_lo[w1]);
                res[nt][0] = q0.x; res[nt][1] = q0.y;
                res[nt][2] = q1.x; res[nt][3] = q1.y;
            }
        }

        float acc[8][4];
        #pragma unroll
        for (int nt = 0; nt < 8; nt++)
            #pragma unroll
            for (int e = 0; e < 4; e++) acc[nt][e] = 0.f;

        #pragma unroll 1
        for (int tap = 0; tap < 3; tap++){
            int rowb = (HALO + wm*16 + r + (tap - 2)*D)*PIT16 + q;
            #pragma unroll 1
            for (int hf = 0; hf < 2; hf++){
                __syncthreads();
                if (hc < 48){ issue_half(hc); hc++; CP_WAIT1(); }
                else        { CP_WAIT0(); }
                __syncthreads();

                if (active){
                    const uint4* bbase = s_b + (size_t)(((cv*6 + tap*2 + hf) & 1))*2048;
                    #pragma unroll
                    for (int kk = 0; kk < 4; kk++){
                        int kt = hf*4 + kk;
                        int w = rowb + kt*8;
                        uint32_t ah[4], al[4];
                        ah[0] = s_hi[w];              ah[1] = s_hi[w + 8*PIT16];
                        ah[2] = s_hi[w + 4];          ah[3] = s_hi[w + 8*PIT16 + 4];
                        al[0] = s_lo[w];              al[1] = s_lo[w + 8*PIT16];
                        al[2] = s_lo[w + 4];          al[3] = s_lo[w + 8*PIT16 + 4];
                        const uint4* bp = bbase + (size_t)(kk*16 + wn*8)*32 + lane;
                        #pragma unroll
                        for (int nt = 0; nt < 8; nt++){
                            uint4 bb = bp[nt*32];
                            MMA_BF16(acc[nt], ah, bb.x, bb.y);
                            MMA_BF16(acc[nt], al, bb.x, bb.y);
                            MMA_BF16(acc[nt], ah, bb.z, bb.w);
                        }
                    }
                }
            }
        }
        __syncthreads();

        if (active){
            const float* ab = &g_ab[cv*2*CC];
            #pragma unroll
            for (int nt = 0; nt < 8; nt++){
                int c = cb + nt*8;
                int w0 = (HALO + r0)*PIT16 + (c >> 1);
                int w1 = (HALO + r1)*PIT16 + (c >> 1);
                float a0 = ab[c], a1 = ab[c+1], b0 = ab[CC+c], b1 = ab[CC+c+1];
                float y00 = gelu_exact(fmaf(acc[nt][0], a0, b0));
                float y01 = gelu_exact(fmaf(acc[nt][1], a1, b1));
                float y10 = gelu_exact(fmaf(acc[nt][2], a0, b0));
                float y11 = gelu_exact(fmaf(acc[nt][3], a1, b1));
                if (second){
                    y00 = gelu_exact(y00 + res[nt][0]);
                    y01 = gelu_exact(y01 + res[nt][1]);
                    y10 = gelu_exact(y10 + res[nt][2]);
                    y11 = gelu_exact(y11 + res[nt][3]);
                }
                uint32_t h0, l0, h1, l1;
                split_pair(y00, y01, h0, l0);
                split_pair(y10, y11, h1, l1);
                s_hi[w0] = h0; s_lo[w0] = l0;
                s_hi[w1] = h1; s_lo[w1] = l1;
            }
        }
    }
    __syncthreads();

    if (tid < CC){
        int w = (HALO + 60)*PIT16 + (tid >> 1);
        float2 v = join_pair(s_hi[w], s_lo[w]);
        g_last[(size_t)p*CC + tid] = (tid & 1) ? v.y : v.x;
    }
}

// ---------------- head: FC(128->128)+GELU, FC(128->1) -------------------------
__global__ void head_kernel(const float* __restrict__ f1w, const float* __restrict__ f1b,
                            const float* __restrict__ f2w, const float* __restrict__ f2b,
                            float* __restrict__ out){
    __shared__ float tv[CC];
    __shared__ float red[4];
    int tid = threadIdx.x;
    int b = blockIdx.x / 7, n = blockIdx.x % 7;
    tv[tid] = g_last[((size_t)(b*NN + n))*CC + tid];
    __syncthreads();
    float z = f1b[tid];
    #pragma unroll 4
    for (int c = 0; c < CC; c++) z = fmaf(f1w[tid*CC + c], tv[c], z);
    z = gelu_exact(z);
    float r = z*f2w[tid];
    #pragma unroll
    for (int o = 16; o; o >>= 1) r += __shfl_xor_sync(0xffffffffu, r, o);
    if ((tid & 31) == 0) red[tid >> 5] = r;
    __syncthreads();
    if (tid == 0) out[blockIdx.x] = red[0] + red[1] + red[2] + red[3] + f2b[0];
}

// -------------------------------------------------------------------------------
extern "C" void kernel_launch(void* const* d_in, const int* in_sizes, int n_in,
                              void* d_out, int out_size){
    const float* x     = (const float*)d_in[0];
    const float* adj   = (const float*)d_in[1];
    const float* gat_w = (const float*)d_in[2];
    const float* a_src = (const float*)d_in[3];
    const float* a_dst = (const float*)d_in[4];
    const float* ln_g  = (const float*)d_in[5];
    const float* ln_b  = (const float*)d_in[6];
    const float* c1w   = (const float*)d_in[7];
    const float* c1b   = (const float*)d_in[8];
    const float* c2w   = (const float*)d_in[9];
    const float* c2b   = (const float*)d_in[10];
    const float* bn1s  = (const float*)d_in[11];
    const float* bn1b  = (const float*)d_in[12];
    const float* bn1m  = (const float*)d_in[13];
    const float* bn1v  = (const float*)d_in[14];
    const float* bn2s  = (const float*)d_in[15];
    const float* bn2b  = (const float*)d_in[16];
    const float* bn2m  = (const float*)d_in[17];
    const float* bn2v  = (const float*)d_in[18];
    const float* f1w   = (const float*)d_in[19];
    const float* f1b   = (const float*)d_in[20];
    const float* f2w   = (const float*)d_in[21];
    const float* f2b   = (const float*)d_in[22];
    float* out = (float*)d_out;

    cudaFuncSetAttribute(gatt_kernel,      cudaFuncAttributeMaxDynamicSharedMemorySize, ATTN_SMEM_BYTES);
    cudaFuncSetAttribute(tcn_fused_kernel, cudaFuncAttributeMaxDynamicSharedMemorySize, TCN_SMEM);

    prep_ab_kernel<<<4, 256>>>(c1b, c2b, bn1s, bn1b, bn1m, bn1v, bn2s, bn2b, bn2m, bn2v);
    prep_wb_kernel<<<(8*3*8*16*32)/256, 256>>>(c1w, c2w);
    gatt_kernel<<<dim3(WKN, BB), 256, ATTN_SMEM_BYTES>>>(x, gat_w, a_src, a_dst,
                                                         adj, ln_g, ln_b);
    tcn_fused_kernel<<<PP, 256, TCN_SMEM>>>();
    head_kernel<<<BB*7, 128>>>(f1w, f1b, f2w, f2b, out);
}